// round 15
// baseline (speedup 1.0000x reference)
#include <cuda_runtime.h>
#include <cuda_fp16.h>
#include <cstdint>

#define BATCH  8192
#define SEQ    100
#define EMBED  50
#define HID    20
#define NLABEL 15
#define VOCAB  50000

// Precomputed P[v][64] = rearranged(emb_table[v] @ W1 + bi1), owner-major:
// owner q (0..3) gets 16 slots: [0..4]=z cols q*5.., [5..9]=r, [10..14]=h, [15]=pad
__device__ float g_P[VOCAB * 64];

// ---------------- helpers ----------------
__device__ __forceinline__ unsigned long long fma2(unsigned long long a,
                                                   unsigned long long b,
                                                   unsigned long long c) {
    unsigned long long d;
    asm("fma.rn.f32x2 %0, %1, %2, %3;" : "=l"(d) : "l"(a), "l"(b), "l"(c));
    return d;
}
__device__ __forceinline__ unsigned long long add2(unsigned long long a,
                                                   unsigned long long b) {
    unsigned long long d;
    asm("add.rn.f32x2 %0, %1, %2;" : "=l"(d) : "l"(a), "l"(b));
    return d;
}
__device__ __forceinline__ unsigned long long pack2(float f) {
    unsigned long long r;
    unsigned int u = __float_as_uint(f);
    asm("mov.b64 %0, {%1, %1};" : "=l"(r) : "r"(u));
    return r;
}
__device__ __forceinline__ float2 unpack2(unsigned long long v) {
    float2 r;
    asm("mov.b64 {%0, %1}, %2;" : "=f"(r.x), "=f"(r.y) : "l"(v));
    return r;
}
// half2 (packed in u32) -> packed f32x2 in u64
__device__ __forceinline__ unsigned long long h2f2(unsigned int h) {
    unsigned long long r;
    asm("{\n\t"
        ".reg .b16 lo, hi;\n\t"
        ".reg .f32 flo, fhi;\n\t"
        "mov.b32 {lo, hi}, %1;\n\t"
        "cvt.f32.f16 flo, lo;\n\t"
        "cvt.f32.f16 fhi, hi;\n\t"
        "mov.b64 %0, {flo, fhi};\n\t"
        "}" : "=l"(r) : "r"(h));
    return r;
}
__device__ __forceinline__ float tanha(float x) {
    float y;
    asm("tanh.approx.f32 %0, %1;" : "=f"(y) : "f"(x));
    return y;
}
// rearranged slot index (0..63) -> original gate column (0..59), or -1 pad
__device__ __forceinline__ int remap_col(int j64) {
    int q = j64 >> 4;
    int jj = j64 & 15;
    if (jj >= 15) return -1;
    int g = jj / 5;
    int l = jj - g * 5;
    return g * HID + q * 5 + l;
}

// ---------------- P precompute ----------------
#define VPB 64
__global__ void __launch_bounds__(256) prep_P_kernel(const float* __restrict__ emb,
                                                     const float* __restrict__ W1,
                                                     const float* __restrict__ b1) {
    __shared__ __align__(16) float W1r[EMBED][64];
    __shared__ float biasr[64];
    __shared__ float embs[VPB][EMBED];
    int tid = threadIdx.x;
    for (int d = tid; d < EMBED * 64; d += 256) {
        int k = d >> 6, j = d & 63;
        int src = remap_col(j);
        W1r[k][j] = (src >= 0) ? W1[k * (3 * HID) + src] : 0.0f;
    }
    if (tid < 64) {
        int src = remap_col(tid);
        biasr[tid] = (src >= 0) ? b1[src] : 0.0f;
    }
    int v0 = blockIdx.x * VPB;
    for (int i = tid; i < VPB * EMBED; i += 256) {
        int vv = i / EMBED, k = i - vv * EMBED;
        int v = v0 + vv;
        embs[vv][k] = (v < VOCAB) ? emb[v * EMBED + k] : 0.0f;
    }
    __syncthreads();
    int d = tid & 63;
    int vbase = tid >> 6;
    #pragma unroll
    for (int i = 0; i < 16; i++) {
        int vl = vbase + 4 * i;
        int v = v0 + vl;
        if (v >= VOCAB) continue;
        float acc = biasr[d];
        #pragma unroll
        for (int k = 0; k < EMBED; k++)
            acc = fmaf(embs[vl][k], W1r[k][d], acc);
        g_P[v * 64 + d] = acc;
    }
}

// ---------------- main fused GRU kernel ----------------
// 8 threads per row-pair: (q owner 0..3) x (s role 0..1), 2 rows/thread.
// All matvecs use OLD h1/h2 (pipelined), so roles run concurrently:
//   s0: U1*h1 (full k) + U2*h2 (k<10)  -> GRU1 gates, P gather, h1 writeback
//   s1: W2*h1 (full k) + U2*h2 (k>=10) -> GRU2 gates (U2 merged via smem),
//       h2 writeback
// Sync is warp-local (__syncwarp on the 8-lane group) -- no block barriers.
// sW (halves): [k][mat][s64], k-stride 192 halves = 48 uint2; U1/W2/U2 at
// uint2 offsets +0/+16/+32 within a k-slice (validated R13 layout).
#define RPB     56
#define PAIRS   28
#define BLOCK   224         // 28 pairs * 8
#define HSTRIDE 21
#define EXQ     17          // u64 per (pair,q): 16 data + 1 pad (bank spread)
#define EXPAIR  (4 * EXQ)   // 68 u64 per pair

__global__ void __launch_bounds__(BLOCK) gru_main_kernel(
    const int*   __restrict__ x,
    const float* __restrict__ U1,
    const float* __restrict__ b1,
    const float* __restrict__ W2,
    const float* __restrict__ U2,
    const float* __restrict__ b2,
    const float* __restrict__ Wd,
    const float* __restrict__ bd,
    float*       __restrict__ out) {

    __shared__ __align__(16) __half sW[HID * 192];                    // 7680 B
    __shared__ __align__(16) unsigned long long sEx[PAIRS * EXPAIR];  // 15232 B
    __shared__ __align__(16) float sbr1[64];
    __shared__ __align__(16) float sbi2[64];
    __shared__ __align__(16) float sbr2[64];
    __shared__ __align__(16) float sWd[HID * 16];
    __shared__ float sbd[16];
    __shared__ __align__(16) float sh1[RPB * HSTRIDE];
    __shared__ __align__(16) float sh2[RPB * HSTRIDE];

    int tid = threadIdx.x;

    // ---- stage interleaved weights (fp16, R13 layout) ----
    for (int d = tid; d < HID * 192; d += BLOCK) {
        int k   = d / 192;
        int rem = d - k * 192;
        int mat = rem >> 6;
        int s64 = rem & 63;            // (j*4+q)*4+c
        int j   = s64 >> 4;
        int q_  = (s64 >> 2) & 3;
        int c   = s64 & 3;
        int src = remap_col(q_ * 16 + (j * 4 + c));
        float v = 0.0f;
        if (src >= 0) {
            int idx = k * (3 * HID) + src;
            v = (mat == 0) ? U1[idx] : (mat == 1) ? W2[idx] : U2[idx];
        }
        sW[d] = __float2half(v);
    }
    if (tid < 64) {
        int src = remap_col(tid);
        float a = 0.0f, bb = 0.0f, c = 0.0f;
        if (src >= 0) {
            a  = b1[3 * HID + src];
            bb = b2[src];
            c  = b2[3 * HID + src];
        }
        sbr1[tid] = a; sbi2[tid] = bb; sbr2[tid] = c;
    }
    for (int d = tid; d < HID * 16; d += BLOCK) {
        int k = d >> 4, j = d & 15;
        sWd[d] = (j < NLABEL) ? Wd[k * NLABEL + j] : 0.0f;
    }
    if (tid < 16) sbd[tid] = (tid < NLABEL) ? bd[tid] : 0.0f;
    __syncthreads();

    int pair = tid >> 3;          // row-pair 0..27
    int s    = (tid >> 2) & 1;    // role
    int q    = tid & 3;           // owner
    int rowa = blockIdx.x * RPB + pair * 2;
    if (rowa >= BATCH) return;    // whole 8-lane group exits together

    unsigned gmask = 0xFFu << ((tid & 31) & ~7);

    float* ph1a = sh1 + (pair * 2) * HSTRIDE;
    float* ph1b = ph1a + HSTRIDE;
    float* ph2a = sh2 + (pair * 2) * HSTRIDE;
    float* ph2b = ph2a + HSTRIDE;

    const int* xa = x + (size_t)rowa * SEQ;
    const int* xb = xa + SEQ;

    const uint2* wfull = reinterpret_cast<const uint2*>(sW) + (s ? 16 : 0);
    const uint2* whalf = reinterpret_cast<const uint2*>(sW) + 32;
    int khalf0 = s * 10;

    const float* bfull_s = s ? sbi2 : sbr1;
    const ulonglong2* bfullv = reinterpret_cast<const ulonglong2*>(bfull_s) + q * 4;
    const ulonglong2* br2v   = reinterpret_cast<const ulonglong2*>(sbr2) + q * 4;
    unsigned long long* exq = sEx + pair * EXPAIR + q * EXQ;

    float h1oa[5], h1ob[5], h2oa[5], h2ob[5];
    #pragma unroll
    for (int i = 0; i < 5; i++) {
        h1oa[i] = 0.f; h1ob[i] = 0.f; h2oa[i] = 0.f; h2ob[i] = 0.f;
    }
    if (s == 1) {
        #pragma unroll
        for (int i = 0; i < 5; i++) { ph2a[q * 5 + i] = 0.f; ph2b[q * 5 + i] = 0.f; }
    }

    int tok_na = 0, tok_nb = 0;

    // -------- prologue: GRU1(0) (s==0; h1=0 -> recurrent side = br1) ------
    if (s == 0) {
        int toka = xa[0], tokb = xb[0];
        const float4* ppa = reinterpret_cast<const float4*>(g_P + (size_t)toka * 64 + q * 16);
        const float4* ppb = reinterpret_cast<const float4*>(g_P + (size_t)tokb * 64 + q * 16);
        float4 a0 = ppa[0], a1 = ppa[1], a2 = ppa[2], a3 = ppa[3];
        float4 b0 = ppb[0], b1_ = ppb[1], b2_ = ppb[2], b3 = ppb[3];
        float pxa[16] = {a0.x,a0.y,a0.z,a0.w, a1.x,a1.y,a1.z,a1.w,
                         a2.x,a2.y,a2.z,a2.w, a3.x,a3.y,a3.z,a3.w};
        float pxb[16] = {b0.x,b0.y,b0.z,b0.w, b1_.x,b1_.y,b1_.z,b1_.w,
                         b2_.x,b2_.y,b2_.z,b2_.w, b3.x,b3.y,b3.z,b3.w};
        #pragma unroll
        for (int i = 0; i < 5; i++) {
            float c0 = sbr1[q * 16 + i];
            float c1 = sbr1[q * 16 + 5 + i];
            float c2 = sbr1[q * 16 + 10 + i];
            {
                float zt = tanha(0.5f * (pxa[i] + c0));
                float r  = 0.5f + 0.5f * tanha(0.5f * (pxa[5 + i] + c1));
                float hh = tanha(pxa[10 + i] + r * c2);
                h1oa[i] = 0.5f * hh - 0.5f * zt * hh;
            }
            {
                float zt = tanha(0.5f * (pxb[i] + c0));
                float r  = 0.5f + 0.5f * tanha(0.5f * (pxb[5 + i] + c1));
                float hh = tanha(pxb[10 + i] + r * c2);
                h1ob[i] = 0.5f * hh - 0.5f * zt * hh;
            }
            ph1a[q * 5 + i] = h1oa[i];
            ph1b[q * 5 + i] = h1ob[i];
        }
        tok_na = xa[1];
        tok_nb = xb[1];
    }
    __syncwarp(gmask);

    // -------- main loop: iteration t does GRU2(t) and GRU1(t+1) --------
    for (int t = 0; t < SEQ - 1; t++) {
        float pxa[16], pxb[16];
        if (s == 0) {   // prefetch input projections for GRU1(t+1)
            const float4* ppa = reinterpret_cast<const float4*>(g_P + (size_t)tok_na * 64 + q * 16);
            const float4* ppb = reinterpret_cast<const float4*>(g_P + (size_t)tok_nb * 64 + q * 16);
            float4 a0 = ppa[0], a1 = ppa[1], a2 = ppa[2], a3 = ppa[3];
            float4 b0 = ppb[0], b1_ = ppb[1], b2_ = ppb[2], b3 = ppb[3];
            pxa[0]=a0.x;pxa[1]=a0.y;pxa[2]=a0.z;pxa[3]=a0.w;
            pxa[4]=a1.x;pxa[5]=a1.y;pxa[6]=a1.z;pxa[7]=a1.w;
            pxa[8]=a2.x;pxa[9]=a2.y;pxa[10]=a2.z;pxa[11]=a2.w;
            pxa[12]=a3.x;pxa[13]=a3.y;pxa[14]=a3.z;pxa[15]=a3.w;
            pxb[0]=b0.x;pxb[1]=b0.y;pxb[2]=b0.z;pxb[3]=b0.w;
            pxb[4]=b1_.x;pxb[5]=b1_.y;pxb[6]=b1_.z;pxb[7]=b1_.w;
            pxb[8]=b2_.x;pxb[9]=b2_.y;pxb[10]=b2_.z;pxb[11]=b2_.w;
            pxb[12]=b3.x;pxb[13]=b3.y;pxb[14]=b3.z;pxb[15]=b3.w;
            int t2 = t + 2;
            int i2 = (t2 < SEQ) ? t2 : (SEQ - 1);
            tok_na = xa[i2];
            tok_nb = xb[i2];
        }

        // ---- full matvec: U1 (s0) / W2 (s1), both rows, k = 0..19 ----
        unsigned long long Fa[8], Fb[8], Pa[8], Pb[8];
        #pragma unroll
        for (int j = 0; j < 4; j++) {
            ulonglong2 tb = bfullv[j];
            Fa[2*j] = tb.x; Fa[2*j+1] = tb.y;
            Fb[2*j] = tb.x; Fb[2*j+1] = tb.y;
            ulonglong2 th = br2v[j];
            unsigned long long z0 = s ? th.x : 0ull;
            unsigned long long z1 = s ? th.y : 0ull;
            Pa[2*j] = z0; Pa[2*j+1] = z1;
            Pb[2*j] = z0; Pb[2*j+1] = z1;
        }
        #pragma unroll 5
        for (int k = 0; k < HID; k++) {
            unsigned long long h1ap = pack2(ph1a[k]);
            unsigned long long h1bp = pack2(ph1b[k]);
            const uint2* wk = wfull + k * 48;
            #pragma unroll
            for (int j = 0; j < 4; j++) {
                uint2 w = wk[j * 4 + q];
                unsigned long long W0 = h2f2(w.x), W1 = h2f2(w.y);
                Fa[2*j]   = fma2(W0, h1ap, Fa[2*j]);
                Fa[2*j+1] = fma2(W1, h1ap, Fa[2*j+1]);
                Fb[2*j]   = fma2(W0, h1bp, Fb[2*j]);
                Fb[2*j+1] = fma2(W1, h1bp, Fb[2*j+1]);
            }
        }
        // ---- half matvec: U2, my 10 k's, both rows ----
        #pragma unroll
        for (int kk = 0; kk < 10; kk++) {
            int k = khalf0 + kk;
            unsigned long long h2ap = pack2(ph2a[k]);
            unsigned long long h2bp = pack2(ph2b[k]);
            const uint2* wk = whalf + k * 48;
            #pragma unroll
            for (int j = 0; j < 4; j++) {
                uint2 w = wk[j * 4 + q];
                unsigned long long W0 = h2f2(w.x), W1 = h2f2(w.y);
                Pa[2*j]   = fma2(W0, h2ap, Pa[2*j]);
                Pa[2*j+1] = fma2(W1, h2ap, Pa[2*j+1]);
                Pb[2*j]   = fma2(W0, h2bp, Pb[2*j]);
                Pb[2*j+1] = fma2(W1, h2bp, Pb[2*j+1]);
            }
        }

        if (s == 0) {     // ship U2 partials to s1
            #pragma unroll
            for (int j = 0; j < 8; j++) { exq[j] = Pa[j]; exq[8 + j] = Pb[j]; }
        }
        __syncwarp(gmask);   // exchange visible; all old-h reads complete

        if (s == 0) {     // GRU1(t+1) gates + h1 writeback
            float aa[16], ab[16];
            #pragma unroll
            for (int j = 0; j < 8; j++) {
                float2 fa = unpack2(Fa[j]); aa[2*j] = fa.x; aa[2*j+1] = fa.y;
                float2 fb = unpack2(Fb[j]); ab[2*j] = fb.x; ab[2*j+1] = fb.y;
            }
            #pragma unroll
            for (int i = 0; i < 5; i++) {
                float zt = tanha(0.5f * (pxa[i] + aa[i]));
                float r  = 0.5f + 0.5f * tanha(0.5f * (pxa[5+i] + aa[5+i]));
                float hh = tanha(pxa[10+i] + r * aa[10+i]);
                float ho = h1oa[i];
                h1oa[i] = 0.5f * (ho + hh) + 0.5f * zt * (ho - hh);
            }
            #pragma unroll
            for (int i = 0; i < 5; i++) {
                float zt = tanha(0.5f * (pxb[i] + ab[i]));
                float r  = 0.5f + 0.5f * tanha(0.5f * (pxb[5+i] + ab[5+i]));
                float hh = tanha(pxb[10+i] + r * ab[10+i]);
                float ho = h1ob[i];
                h1ob[i] = 0.5f * (ho + hh) + 0.5f * zt * (ho - hh);
            }
            #pragma unroll
            for (int i = 0; i < 5; i++) {
                ph1a[q * 5 + i] = h1oa[i];
                ph1b[q * 5 + i] = h1ob[i];
            }
        } else {          // merge U2 halves, GRU2(t) gates + h2 writeback
            #pragma unroll
            for (int j = 0; j < 8; j++) {
                Pa[j] = add2(Pa[j], exq[j]);
                Pb[j] = add2(Pb[j], exq[8 + j]);
            }
            float bxa[16], bxb[16], bha[16], bhb[16];
            #pragma unroll
            for (int j = 0; j < 8; j++) {
                float2 fx = unpack2(Fa[j]); bxa[2*j] = fx.x; bxa[2*j+1] = fx.y;
                float2 fy = unpack2(Fb[j]); bxb[2*j] = fy.x; bxb[2*j+1] = fy.y;
                float2 fh = unpack2(Pa[j]); bha[2*j] = fh.x; bha[2*j+1] = fh.y;
                float2 fg = unpack2(Pb[j]); bhb[2*j] = fg.x; bhb[2*j+1] = fg.y;
            }
            #pragma unroll
            for (int i = 0; i < 5; i++) {
                float zt = tanha(0.5f * (bxa[i] + bha[i]));
                float r  = 0.5f + 0.5f * tanha(0.5f * (bxa[5+i] + bha[5+i]));
                float hh = tanha(bxa[10+i] + r * bha[10+i]);
                float ho = h2oa[i];
                h2oa[i] = 0.5f * (ho + hh) + 0.5f * zt * (ho - hh);
            }
            #pragma unroll
            for (int i = 0; i < 5; i++) {
                float zt = tanha(0.5f * (bxb[i] + bhb[i]));
                float r  = 0.5f + 0.5f * tanha(0.5f * (bxb[5+i] + bhb[5+i]));
                float hh = tanha(bxb[10+i] + r * bhb[10+i]);
                float ho = h2ob[i];
                h2ob[i] = 0.5f * (ho + hh) + 0.5f * zt * (ho - hh);
            }
            #pragma unroll
            for (int i = 0; i < 5; i++) {
                ph2a[q * 5 + i] = h2oa[i];
                ph2b[q * 5 + i] = h2ob[i];
            }
        }
        __syncwarp(gmask);   // new h visible to group
    }

    // -------- epilogue: GRU2(SEQ-1) --------
    {
        unsigned long long Fa[8], Fb[8], Pa[8], Pb[8];
        #pragma unroll
        for (int j = 0; j < 4; j++) {
            ulonglong2 tx = reinterpret_cast<const ulonglong2*>(sbi2)[q * 4 + j];
            Fa[2*j] = tx.x; Fa[2*j+1] = tx.y;
            Fb[2*j] = tx.x; Fb[2*j+1] = tx.y;
            ulonglong2 th = br2v[j];
            unsigned long long z0 = s ? th.x : 0ull;
            unsigned long long z1 = s ? th.y : 0ull;
            Pa[2*j] = z0; Pa[2*j+1] = z1;
            Pb[2*j] = z0; Pb[2*j+1] = z1;
        }
        if (s == 1) {   // full W2 matvec (only s1 needs it)
            const uint2* wf = reinterpret_cast<const uint2*>(sW) + 16;
            #pragma unroll 5
            for (int k = 0; k < HID; k++) {
                unsigned long long h1ap = pack2(ph1a[k]);
                unsigned long long h1bp = pack2(ph1b[k]);
                const uint2* wk = wf + k * 48;
                #pragma unroll
                for (int j = 0; j < 4; j++) {
                    uint2 w = wk[j * 4 + q];
                    unsigned long long W0 = h2f2(w.x), W1 = h2f2(w.y);
                    Fa[2*j]   = fma2(W0, h1ap, Fa[2*j]);
                    Fa[2*j+1] = fma2(W1, h1ap, Fa[2*j+1]);
                    Fb[2*j]   = fma2(W0, h1bp, Fb[2*j]);
                    Fb[2*j+1] = fma2(W1, h1bp, Fb[2*j+1]);
                }
            }
        }
        #pragma unroll
        for (int kk = 0; kk < 10; kk++) {
            int k = khalf0 + kk;
            unsigned long long h2ap = pack2(ph2a[k]);
            unsigned long long h2bp = pack2(ph2b[k]);
            const uint2* wk = whalf + k * 48;
            #pragma unroll
            for (int j = 0; j < 4; j++) {
                uint2 w = wk[j * 4 + q];
                unsigned long long W0 = h2f2(w.x), W1 = h2f2(w.y);
                Pa[2*j]   = fma2(W0, h2ap, Pa[2*j]);
                Pa[2*j+1] = fma2(W1, h2ap, Pa[2*j+1]);
                Pb[2*j]   = fma2(W0, h2bp, Pb[2*j]);
                Pb[2*j+1] = fma2(W1, h2bp, Pb[2*j+1]);
            }
        }
        if (s == 0) {
            #pragma unroll
            for (int j = 0; j < 8; j++) { exq[j] = Pa[j]; exq[8 + j] = Pb[j]; }
        }
        __syncwarp(gmask);
        if (s == 1) {
            #pragma unroll
            for (int j = 0; j < 8; j++) {
                Pa[j] = add2(Pa[j], exq[j]);
                Pb[j] = add2(Pb[j], exq[8 + j]);
            }
            float bxa[16], bxb[16], bha[16], bhb[16];
            #pragma unroll
            for (int j = 0; j < 8; j++) {
                float2 fx = unpack2(Fa[j]); bxa[2*j] = fx.x; bxa[2*j+1] = fx.y;
                float2 fy = unpack2(Fb[j]); bxb[2*j] = fy.x; bxb[2*j+1] = fy.y;
                float2 fh = unpack2(Pa[j]); bha[2*j] = fh.x; bha[2*j+1] = fh.y;
                float2 fg = unpack2(Pb[j]); bhb[2*j] = fg.x; bhb[2*j+1] = fg.y;
            }
            #pragma unroll
            for (int i = 0; i < 5; i++) {
                float zt = tanha(0.5f * (bxa[i] + bha[i]));
                float r  = 0.5f + 0.5f * tanha(0.5f * (bxa[5+i] + bha[5+i]));
                float hh = tanha(bxa[10+i] + r * bha[10+i]);
                float ho = h2oa[i];
                h2oa[i] = 0.5f * (ho + hh) + 0.5f * zt * (ho - hh);
            }
            #pragma unroll
            for (int i = 0; i < 5; i++) {
                float zt = tanha(0.5f * (bxb[i] + bhb[i]));
                float r  = 0.5f + 0.5f * tanha(0.5f * (bxb[5+i] + bhb[5+i]));
                float hh = tanha(bxb[10+i] + r * bhb[10+i]);
                float ho = h2ob[i];
                h2ob[i] = 0.5f * (ho + hh) + 0.5f * zt * (ho - hh);
            }
            #pragma unroll
            for (int i = 0; i < 5; i++) {
                ph2a[q * 5 + i] = h2oa[i];
                ph2b[q * 5 + i] = h2ob[i];
            }
        }
        __syncwarp(gmask);
    }

    // -------- dense head: s0 -> row a, s1 -> row b; cols q*4..q*4+3 --------
    {
        int myrow = rowa + s;
        const float* ph2m = s ? ph2b : ph2a;
        float hv[HID];
        #pragma unroll
        for (int k = 0; k < HID; k++) hv[k] = ph2m[k];
        #pragma unroll
        for (int c = 0; c < 4; c++) {
            int col = q * 4 + c;
            if (col >= NLABEL) break;
            float acc = sbd[col];
            #pragma unroll
            for (int k = 0; k < HID; k++)
                acc = fmaf(hv[k], sWd[k * 16 + col], acc);
            out[(size_t)myrow * NLABEL + col] = acc;
        }
    }
}

// ---------------- launch ----------------
extern "C" void kernel_launch(void* const* d_in, const int* in_sizes, int n_in,
                              void* d_out, int out_size) {
    const int*   x    = (const int*)  d_in[0];
    const float* emb  = (const float*)d_in[1];
    const float* W1   = (const float*)d_in[2];
    const float* U1   = (const float*)d_in[3];
    const float* b1   = (const float*)d_in[4];
    const float* W2   = (const float*)d_in[5];
    const float* U2   = (const float*)d_in[6];
    const float* b2   = (const float*)d_in[7];
    const float* Wd   = (const float*)d_in[8];
    const float* bd   = (const float*)d_in[9];
    float* out = (float*)d_out;

    prep_P_kernel<<<(VOCAB + VPB - 1) / VPB, 256>>>(emb, W1, b1);
    gru_main_kernel<<<(BATCH + RPB - 1) / RPB, BLOCK>>>(x, U1, b1, W2, U2, b2, Wd, bd, out);
}

// round 16
// speedup vs baseline: 1.7276x; 1.7276x over previous
#include <cuda_runtime.h>
#include <cuda_fp16.h>
#include <cstdint>

#define BATCH  8192
#define SEQ    100
#define EMBED  50
#define HID    20
#define NLABEL 15
#define VOCAB  50000

// Precomputed P[v][64] = rearranged(emb_table[v] @ W1 + bi1), owner-major:
// owner q (0..3) gets 16 slots: [0..4]=z cols q*5.., [5..9]=r, [10..14]=h, [15]=pad
__device__ float g_P[VOCAB * 64];

// ---------------- helpers ----------------
__device__ __forceinline__ unsigned long long fma2(unsigned long long a,
                                                   unsigned long long b,
                                                   unsigned long long c) {
    unsigned long long d;
    asm("fma.rn.f32x2 %0, %1, %2, %3;" : "=l"(d) : "l"(a), "l"(b), "l"(c));
    return d;
}
__device__ __forceinline__ unsigned long long add2(unsigned long long a,
                                                   unsigned long long b) {
    unsigned long long d;
    asm("add.rn.f32x2 %0, %1, %2;" : "=l"(d) : "l"(a), "l"(b));
    return d;
}
__device__ __forceinline__ unsigned long long pack2(float f) {
    unsigned long long r;
    unsigned int u = __float_as_uint(f);
    asm("mov.b64 %0, {%1, %1};" : "=l"(r) : "r"(u));
    return r;
}
__device__ __forceinline__ float2 unpack2(unsigned long long v) {
    float2 r;
    asm("mov.b64 {%0, %1}, %2;" : "=f"(r.x), "=f"(r.y) : "l"(v));
    return r;
}
// half2 (packed in u32) -> packed f32x2 in u64
__device__ __forceinline__ unsigned long long h2f2(unsigned int h) {
    unsigned long long r;
    asm("{\n\t"
        ".reg .b16 lo, hi;\n\t"
        ".reg .f32 flo, fhi;\n\t"
        "mov.b32 {lo, hi}, %1;\n\t"
        "cvt.f32.f16 flo, lo;\n\t"
        "cvt.f32.f16 fhi, hi;\n\t"
        "mov.b64 %0, {flo, fhi};\n\t"
        "}" : "=l"(r) : "r"(h));
    return r;
}
__device__ __forceinline__ float tanha(float x) {
    float y;
    asm("tanh.approx.f32 %0, %1;" : "=f"(y) : "f"(x));
    return y;
}
// rearranged slot index (0..63) -> original gate column (0..59), or -1 pad
__device__ __forceinline__ int remap_col(int j64) {
    int q = j64 >> 4;
    int jj = j64 & 15;
    if (jj >= 15) return -1;
    int g = jj / 5;
    int l = jj - g * 5;
    return g * HID + q * 5 + l;
}

// ---------------- P precompute ----------------
#define VPB 64
__global__ void __launch_bounds__(256) prep_P_kernel(const float* __restrict__ emb,
                                                     const float* __restrict__ W1,
                                                     const float* __restrict__ b1) {
    __shared__ __align__(16) float W1r[EMBED][64];
    __shared__ float biasr[64];
    __shared__ float embs[VPB][EMBED];
    int tid = threadIdx.x;
    for (int d = tid; d < EMBED * 64; d += 256) {
        int k = d >> 6, j = d & 63;
        int src = remap_col(j);
        W1r[k][j] = (src >= 0) ? W1[k * (3 * HID) + src] : 0.0f;
    }
    if (tid < 64) {
        int src = remap_col(tid);
        biasr[tid] = (src >= 0) ? b1[src] : 0.0f;
    }
    int v0 = blockIdx.x * VPB;
    for (int i = tid; i < VPB * EMBED; i += 256) {
        int vv = i / EMBED, k = i - vv * EMBED;
        int v = v0 + vv;
        embs[vv][k] = (v < VOCAB) ? emb[v * EMBED + k] : 0.0f;
    }
    __syncthreads();
    int d = tid & 63;
    int vbase = tid >> 6;
    #pragma unroll
    for (int i = 0; i < 16; i++) {
        int vl = vbase + 4 * i;
        int v = v0 + vl;
        if (v >= VOCAB) continue;
        float acc = biasr[d];
        #pragma unroll
        for (int k = 0; k < EMBED; k++)
            acc = fmaf(embs[vl][k], W1r[k][d], acc);
        g_P[v * 64 + d] = acc;
    }
}

// ---------------- main fused GRU kernel ----------------
// 8 threads per row-pair: (q owner 0..3) x (s role 0..1), 2 rows/thread.
// All matvecs use OLD h1/h2 (pipelined), so roles run concurrently:
//   s0: U1*h1 (full k) + U2*h2 (k<10)  -> GRU1 gates, P gather, h1 writeback
//   s1: W2*h1 (full k) + U2*h2 (k>=10) -> GRU2 gates (U2 merged via smem),
//       h2 writeback
// Sync is warp-local (__syncwarp on the 8-lane group) -- no block barriers.
//
// Weight layout (CONFLICT-FREE, fixes R15): uint2 index =
//   k*50 + j*12 + mat*4 + q     (k-stride padded 48->50 uint2)
// For one weight-load instruction, warp lanes (s,q) hit uint2 s*4+q (0..7)
// = 16 distinct words; U2 half-split (Delta = 10*50 u2 = 1000 words = 8 mod
// 32) also disjoint -> zero bank conflicts.
#define RPB     56
#define PAIRS   28
#define BLOCK   224         // 28 pairs * 8
#define HSTRIDE 21
#define KU2     50          // uint2 per k-slice (padded)
#define EXQ     17          // u64 per (pair,q): 16 data + 1 pad (bank spread)
#define EXPAIR  (4 * EXQ)   // 68 u64 per pair

__global__ void __launch_bounds__(BLOCK) gru_main_kernel(
    const int*   __restrict__ x,
    const float* __restrict__ U1,
    const float* __restrict__ b1,
    const float* __restrict__ W2,
    const float* __restrict__ U2,
    const float* __restrict__ b2,
    const float* __restrict__ Wd,
    const float* __restrict__ bd,
    float*       __restrict__ out) {

    __shared__ __align__(16) __half sW[HID * KU2 * 4];                // 8000 B
    __shared__ __align__(16) unsigned long long sEx[PAIRS * EXPAIR];  // 15232 B
    __shared__ __align__(16) float sbr1[64];
    __shared__ __align__(16) float sbi2[64];
    __shared__ __align__(16) float sbr2[64];
    __shared__ __align__(16) float sWd[HID * 16];
    __shared__ float sbd[16];
    __shared__ __align__(16) float sh1[RPB * HSTRIDE];
    __shared__ __align__(16) float sh2[RPB * HSTRIDE];

    int tid = threadIdx.x;

    // ---- stage weights fp16, layout [k][j][mat][q] halves, k-stride 200 ----
    for (int d = tid; d < HID * KU2 * 4; d += BLOCK) {
        int k   = d / (KU2 * 4);
        int rem = d - k * (KU2 * 4);
        int u2i = rem >> 2;          // 0..49
        int c   = rem & 3;
        float v = 0.0f;
        if (u2i < 48) {
            int j   = u2i / 12;      // 0..3
            int r2  = u2i - j * 12;
            int mat = r2 >> 2;       // 0..2
            int q_  = r2 & 3;
            int src = remap_col(q_ * 16 + (j * 4 + c));
            if (src >= 0) {
                int idx = k * (3 * HID) + src;
                v = (mat == 0) ? U1[idx] : (mat == 1) ? W2[idx] : U2[idx];
            }
        }
        sW[d] = __float2half(v);
    }
    if (tid < 64) {
        int src = remap_col(tid);
        float a = 0.0f, bb = 0.0f, c = 0.0f;
        if (src >= 0) {
            a  = b1[3 * HID + src];
            bb = b2[src];
            c  = b2[3 * HID + src];
        }
        sbr1[tid] = a; sbi2[tid] = bb; sbr2[tid] = c;
    }
    for (int d = tid; d < HID * 16; d += BLOCK) {
        int k = d >> 4, j = d & 15;
        sWd[d] = (j < NLABEL) ? Wd[k * NLABEL + j] : 0.0f;
    }
    if (tid < 16) sbd[tid] = (tid < NLABEL) ? bd[tid] : 0.0f;
    __syncthreads();

    int pair = tid >> 3;          // row-pair 0..27
    int s    = (tid >> 2) & 1;    // role
    int q    = tid & 3;           // owner
    int rowa = blockIdx.x * RPB + pair * 2;
    if (rowa >= BATCH) return;    // whole 8-lane group exits together

    unsigned gmask = 0xFFu << ((tid & 31) & ~7);

    float* ph1a = sh1 + (pair * 2) * HSTRIDE;
    float* ph1b = ph1a + HSTRIDE;
    float* ph2a = sh2 + (pair * 2) * HSTRIDE;
    float* ph2b = ph2a + HSTRIDE;

    const int* xa = x + (size_t)rowa * SEQ;
    const int* xb = xa + SEQ;

    const uint2* sWu2  = reinterpret_cast<const uint2*>(sW);
    const uint2* wfull = sWu2 + s * 4 + q;   // mat = s (U1 or W2), my q
    const uint2* whalf = sWu2 + 8 + q;       // mat = 2 (U2), my q
    int khalf0 = s * 10;

    const float* bfull_s = s ? sbi2 : sbr1;
    const ulonglong2* bfullv = reinterpret_cast<const ulonglong2*>(bfull_s) + q * 4;
    const ulonglong2* br2v   = reinterpret_cast<const ulonglong2*>(sbr2) + q * 4;
    unsigned long long* exq = sEx + pair * EXPAIR + q * EXQ;

    float h1oa[5], h1ob[5], h2oa[5], h2ob[5];
    #pragma unroll
    for (int i = 0; i < 5; i++) {
        h1oa[i] = 0.f; h1ob[i] = 0.f; h2oa[i] = 0.f; h2ob[i] = 0.f;
    }
    if (s == 1) {
        #pragma unroll
        for (int i = 0; i < 5; i++) { ph2a[q * 5 + i] = 0.f; ph2b[q * 5 + i] = 0.f; }
    }

    int tok_na = 0, tok_nb = 0;

    // -------- prologue: GRU1(0) (s==0; h1=0 -> recurrent side = br1) ------
    if (s == 0) {
        int toka = xa[0], tokb = xb[0];
        const float4* ppa = reinterpret_cast<const float4*>(g_P + (size_t)toka * 64 + q * 16);
        const float4* ppb = reinterpret_cast<const float4*>(g_P + (size_t)tokb * 64 + q * 16);
        float4 a0 = ppa[0], a1 = ppa[1], a2 = ppa[2], a3 = ppa[3];
        float4 b0 = ppb[0], b1_ = ppb[1], b2_ = ppb[2], b3 = ppb[3];
        float pxa[16] = {a0.x,a0.y,a0.z,a0.w, a1.x,a1.y,a1.z,a1.w,
                         a2.x,a2.y,a2.z,a2.w, a3.x,a3.y,a3.z,a3.w};
        float pxb[16] = {b0.x,b0.y,b0.z,b0.w, b1_.x,b1_.y,b1_.z,b1_.w,
                         b2_.x,b2_.y,b2_.z,b2_.w, b3.x,b3.y,b3.z,b3.w};
        #pragma unroll
        for (int i = 0; i < 5; i++) {
            float c0 = sbr1[q * 16 + i];
            float c1 = sbr1[q * 16 + 5 + i];
            float c2 = sbr1[q * 16 + 10 + i];
            {
                float zt = tanha(0.5f * (pxa[i] + c0));
                float r  = 0.5f + 0.5f * tanha(0.5f * (pxa[5 + i] + c1));
                float hh = tanha(pxa[10 + i] + r * c2);
                h1oa[i] = 0.5f * hh - 0.5f * zt * hh;
            }
            {
                float zt = tanha(0.5f * (pxb[i] + c0));
                float r  = 0.5f + 0.5f * tanha(0.5f * (pxb[5 + i] + c1));
                float hh = tanha(pxb[10 + i] + r * c2);
                h1ob[i] = 0.5f * hh - 0.5f * zt * hh;
            }
            ph1a[q * 5 + i] = h1oa[i];
            ph1b[q * 5 + i] = h1ob[i];
        }
        tok_na = xa[1];
        tok_nb = xb[1];
    }
    __syncwarp(gmask);

    // -------- main loop: iteration t does GRU2(t) and GRU1(t+1) --------
    for (int t = 0; t < SEQ - 1; t++) {
        float pxa[16], pxb[16];
        if (s == 0) {   // prefetch input projections for GRU1(t+1)
            const float4* ppa = reinterpret_cast<const float4*>(g_P + (size_t)tok_na * 64 + q * 16);
            const float4* ppb = reinterpret_cast<const float4*>(g_P + (size_t)tok_nb * 64 + q * 16);
            float4 a0 = ppa[0], a1 = ppa[1], a2 = ppa[2], a3 = ppa[3];
            float4 b0 = ppb[0], b1_ = ppb[1], b2_ = ppb[2], b3 = ppb[3];
            pxa[0]=a0.x;pxa[1]=a0.y;pxa[2]=a0.z;pxa[3]=a0.w;
            pxa[4]=a1.x;pxa[5]=a1.y;pxa[6]=a1.z;pxa[7]=a1.w;
            pxa[8]=a2.x;pxa[9]=a2.y;pxa[10]=a2.z;pxa[11]=a2.w;
            pxa[12]=a3.x;pxa[13]=a3.y;pxa[14]=a3.z;pxa[15]=a3.w;
            pxb[0]=b0.x;pxb[1]=b0.y;pxb[2]=b0.z;pxb[3]=b0.w;
            pxb[4]=b1_.x;pxb[5]=b1_.y;pxb[6]=b1_.z;pxb[7]=b1_.w;
            pxb[8]=b2_.x;pxb[9]=b2_.y;pxb[10]=b2_.z;pxb[11]=b2_.w;
            pxb[12]=b3.x;pxb[13]=b3.y;pxb[14]=b3.z;pxb[15]=b3.w;
            int t2 = t + 2;
            int i2 = (t2 < SEQ) ? t2 : (SEQ - 1);
            tok_na = xa[i2];
            tok_nb = xb[i2];
        }

        // ---- full matvec: U1 (s0) / W2 (s1), both rows, k = 0..19 ----
        unsigned long long Fa[8], Fb[8], Pa[8], Pb[8];
        #pragma unroll
        for (int j = 0; j < 4; j++) {
            ulonglong2 tb = bfullv[j];
            Fa[2*j] = tb.x; Fa[2*j+1] = tb.y;
            Fb[2*j] = tb.x; Fb[2*j+1] = tb.y;
            ulonglong2 th = br2v[j];
            unsigned long long z0 = s ? th.x : 0ull;
            unsigned long long z1 = s ? th.y : 0ull;
            Pa[2*j] = z0; Pa[2*j+1] = z1;
            Pb[2*j] = z0; Pb[2*j+1] = z1;
        }
        #pragma unroll 5
        for (int k = 0; k < HID; k++) {
            unsigned long long h1ap = pack2(ph1a[k]);
            unsigned long long h1bp = pack2(ph1b[k]);
            const uint2* wk = wfull + k * KU2;
            #pragma unroll
            for (int j = 0; j < 4; j++) {
                uint2 w = wk[j * 12];
                unsigned long long W0 = h2f2(w.x), W1 = h2f2(w.y);
                Fa[2*j]   = fma2(W0, h1ap, Fa[2*j]);
                Fa[2*j+1] = fma2(W1, h1ap, Fa[2*j+1]);
                Fb[2*j]   = fma2(W0, h1bp, Fb[2*j]);
                Fb[2*j+1] = fma2(W1, h1bp, Fb[2*j+1]);
            }
        }
        // ---- half matvec: U2, my 10 k's, both rows ----
        #pragma unroll
        for (int kk = 0; kk < 10; kk++) {
            int k = khalf0 + kk;
            unsigned long long h2ap = pack2(ph2a[k]);
            unsigned long long h2bp = pack2(ph2b[k]);
            const uint2* wk = whalf + k * KU2;
            #pragma unroll
            for (int j = 0; j < 4; j++) {
                uint2 w = wk[j * 12];
                unsigned long long W0 = h2f2(w.x), W1 = h2f2(w.y);
                Pa[2*j]   = fma2(W0, h2ap, Pa[2*j]);
                Pa[2*j+1] = fma2(W1, h2ap, Pa[2*j+1]);
                Pb[2*j]   = fma2(W0, h2bp, Pb[2*j]);
                Pb[2*j+1] = fma2(W1, h2bp, Pb[2*j+1]);
            }
        }

        if (s == 0) {     // ship U2 partials to s1
            #pragma unroll
            for (int j = 0; j < 8; j++) { exq[j] = Pa[j]; exq[8 + j] = Pb[j]; }
        }
        __syncwarp(gmask);   // exchange visible; all old-h reads complete

        if (s == 0) {     // GRU1(t+1) gates + h1 writeback
            float aa[16], ab[16];
            #pragma unroll
            for (int j = 0; j < 8; j++) {
                float2 fa = unpack2(Fa[j]); aa[2*j] = fa.x; aa[2*j+1] = fa.y;
                float2 fb = unpack2(Fb[j]); ab[2*j] = fb.x; ab[2*j+1] = fb.y;
            }
            #pragma unroll
            for (int i = 0; i < 5; i++) {
                float zt = tanha(0.5f * (pxa[i] + aa[i]));
                float r  = 0.5f + 0.5f * tanha(0.5f * (pxa[5+i] + aa[5+i]));
                float hh = tanha(pxa[10+i] + r * aa[10+i]);
                float ho = h1oa[i];
                h1oa[i] = 0.5f * (ho + hh) + 0.5f * zt * (ho - hh);
            }
            #pragma unroll
            for (int i = 0; i < 5; i++) {
                float zt = tanha(0.5f * (pxb[i] + ab[i]));
                float r  = 0.5f + 0.5f * tanha(0.5f * (pxb[5+i] + ab[5+i]));
                float hh = tanha(pxb[10+i] + r * ab[10+i]);
                float ho = h1ob[i];
                h1ob[i] = 0.5f * (ho + hh) + 0.5f * zt * (ho - hh);
            }
            #pragma unroll
            for (int i = 0; i < 5; i++) {
                ph1a[q * 5 + i] = h1oa[i];
                ph1b[q * 5 + i] = h1ob[i];
            }
        } else {          // merge U2 halves, GRU2(t) gates + h2 writeback
            #pragma unroll
            for (int j = 0; j < 8; j++) {
                Pa[j] = add2(Pa[j], exq[j]);
                Pb[j] = add2(Pb[j], exq[8 + j]);
            }
            float bxa[16], bxb[16], bha[16], bhb[16];
            #pragma unroll
            for (int j = 0; j < 8; j++) {
                float2 fx = unpack2(Fa[j]); bxa[2*j] = fx.x; bxa[2*j+1] = fx.y;
                float2 fy = unpack2(Fb[j]); bxb[2*j] = fy.x; bxb[2*j+1] = fy.y;
                float2 fh = unpack2(Pa[j]); bha[2*j] = fh.x; bha[2*j+1] = fh.y;
                float2 fg = unpack2(Pb[j]); bhb[2*j] = fg.x; bhb[2*j+1] = fg.y;
            }
            #pragma unroll
            for (int i = 0; i < 5; i++) {
                float zt = tanha(0.5f * (bxa[i] + bha[i]));
                float r  = 0.5f + 0.5f * tanha(0.5f * (bxa[5+i] + bha[5+i]));
                float hh = tanha(bxa[10+i] + r * bha[10+i]);
                float ho = h2oa[i];
                h2oa[i] = 0.5f * (ho + hh) + 0.5f * zt * (ho - hh);
            }
            #pragma unroll
            for (int i = 0; i < 5; i++) {
                float zt = tanha(0.5f * (bxb[i] + bhb[i]));
                float r  = 0.5f + 0.5f * tanha(0.5f * (bxb[5+i] + bhb[5+i]));
                float hh = tanha(bxb[10+i] + r * bhb[10+i]);
                float ho = h2ob[i];
                h2ob[i] = 0.5f * (ho + hh) + 0.5f * zt * (ho - hh);
            }
            #pragma unroll
            for (int i = 0; i < 5; i++) {
                ph2a[q * 5 + i] = h2oa[i];
                ph2b[q * 5 + i] = h2ob[i];
            }
        }
        __syncwarp(gmask);   // new h visible to group
    }

    // -------- epilogue: GRU2(SEQ-1) --------
    {
        unsigned long long Fa[8], Fb[8], Pa[8], Pb[8];
        #pragma unroll
        for (int j = 0; j < 4; j++) {
            ulonglong2 tx = reinterpret_cast<const ulonglong2*>(sbi2)[q * 4 + j];
            Fa[2*j] = tx.x; Fa[2*j+1] = tx.y;
            Fb[2*j] = tx.x; Fb[2*j+1] = tx.y;
            ulonglong2 th = br2v[j];
            unsigned long long z0 = s ? th.x : 0ull;
            unsigned long long z1 = s ? th.y : 0ull;
            Pa[2*j] = z0; Pa[2*j+1] = z1;
            Pb[2*j] = z0; Pb[2*j+1] = z1;
        }
        if (s == 1) {   // full W2 matvec (only s1 needs it); mat=1 -> +4
            const uint2* wf = sWu2 + 4 + q;
            #pragma unroll 5
            for (int k = 0; k < HID; k++) {
                unsigned long long h1ap = pack2(ph1a[k]);
                unsigned long long h1bp = pack2(ph1b[k]);
                const uint2* wk = wf + k * KU2;
                #pragma unroll
                for (int j = 0; j < 4; j++) {
                    uint2 w = wk[j * 12];
                    unsigned long long W0 = h2f2(w.x), W1 = h2f2(w.y);
                    Fa[2*j]   = fma2(W0, h1ap, Fa[2*j]);
                    Fa[2*j+1] = fma2(W1, h1ap, Fa[2*j+1]);
                    Fb[2*j]   = fma2(W0, h1bp, Fb[2*j]);
                    Fb[2*j+1] = fma2(W1, h1bp, Fb[2*j+1]);
                }
            }
        }
        #pragma unroll
        for (int kk = 0; kk < 10; kk++) {
            int k = khalf0 + kk;
            unsigned long long h2ap = pack2(ph2a[k]);
            unsigned long long h2bp = pack2(ph2b[k]);
            const uint2* wk = whalf + k * KU2;
            #pragma unroll
            for (int j = 0; j < 4; j++) {
                uint2 w = wk[j * 12];
                unsigned long long W0 = h2f2(w.x), W1 = h2f2(w.y);
                Pa[2*j]   = fma2(W0, h2ap, Pa[2*j]);
                Pa[2*j+1] = fma2(W1, h2ap, Pa[2*j+1]);
                Pb[2*j]   = fma2(W0, h2bp, Pb[2*j]);
                Pb[2*j+1] = fma2(W1, h2bp, Pb[2*j+1]);
            }
        }
        if (s == 0) {
            #pragma unroll
            for (int j = 0; j < 8; j++) { exq[j] = Pa[j]; exq[8 + j] = Pb[j]; }
        }
        __syncwarp(gmask);
        if (s == 1) {
            #pragma unroll
            for (int j = 0; j < 8; j++) {
                Pa[j] = add2(Pa[j], exq[j]);
                Pb[j] = add2(Pb[j], exq[8 + j]);
            }
            float bxa[16], bxb[16], bha[16], bhb[16];
            #pragma unroll
            for (int j = 0; j < 8; j++) {
                float2 fx = unpack2(Fa[j]); bxa[2*j] = fx.x; bxa[2*j+1] = fx.y;
                float2 fy = unpack2(Fb[j]); bxb[2*j] = fy.x; bxb[2*j+1] = fy.y;
                float2 fh = unpack2(Pa[j]); bha[2*j] = fh.x; bha[2*j+1] = fh.y;
                float2 fg = unpack2(Pb[j]); bhb[2*j] = fg.x; bhb[2*j+1] = fg.y;
            }
            #pragma unroll
            for (int i = 0; i < 5; i++) {
                float zt = tanha(0.5f * (bxa[i] + bha[i]));
                float r  = 0.5f + 0.5f * tanha(0.5f * (bxa[5+i] + bha[5+i]));
                float hh = tanha(bxa[10+i] + r * bha[10+i]);
                float ho = h2oa[i];
                h2oa[i] = 0.5f * (ho + hh) + 0.5f * zt * (ho - hh);
            }
            #pragma unroll
            for (int i = 0; i < 5; i++) {
                float zt = tanha(0.5f * (bxb[i] + bhb[i]));
                float r  = 0.5f + 0.5f * tanha(0.5f * (bxb[5+i] + bhb[5+i]));
                float hh = tanha(bxb[10+i] + r * bhb[10+i]);
                float ho = h2ob[i];
                h2ob[i] = 0.5f * (ho + hh) + 0.5f * zt * (ho - hh);
            }
            #pragma unroll
            for (int i = 0; i < 5; i++) {
                ph2a[q * 5 + i] = h2oa[i];
                ph2b[q * 5 + i] = h2ob[i];
            }
        }
        __syncwarp(gmask);
    }

    // -------- dense head: s0 -> row a, s1 -> row b; cols q*4..q*4+3 --------
    {
        int myrow = rowa + s;
        const float* ph2m = s ? ph2b : ph2a;
        float hv[HID];
        #pragma unroll
        for (int k = 0; k < HID; k++) hv[k] = ph2m[k];
        #pragma unroll
        for (int c = 0; c < 4; c++) {
            int col = q * 4 + c;
            if (col >= NLABEL) break;
            float acc = sbd[col];
            #pragma unroll
            for (int k = 0; k < HID; k++)
                acc = fmaf(hv[k], sWd[k * 16 + col], acc);
            out[(size_t)myrow * NLABEL + col] = acc;
        }
    }
}

// ---------------- launch ----------------
extern "C" void kernel_launch(void* const* d_in, const int* in_sizes, int n_in,
                              void* d_out, int out_size) {
    const int*   x    = (const int*)  d_in[0];
    const float* emb  = (const float*)d_in[1];
    const float* W1   = (const float*)d_in[2];
    const float* U1   = (const float*)d_in[3];
    const float* b1   = (const float*)d_in[4];
    const float* W2   = (const float*)d_in[5];
    const float* U2   = (const float*)d_in[6];
    const float* b2   = (const float*)d_in[7];
    const float* Wd   = (const float*)d_in[8];
    const float* bd   = (const float*)d_in[9];
    float* out = (float*)d_out;

    prep_P_kernel<<<(VOCAB + VPB - 1) / VPB, 256>>>(emb, W1, b1);
    gru_main_kernel<<<(BATCH + RPB - 1) / RPB, BLOCK>>>(x, U1, b1, W2, U2, b2, Wd, bd, out);
}

// round 17
// speedup vs baseline: 3.3715x; 1.9515x over previous
#include <cuda_runtime.h>
#include <cuda_fp16.h>
#include <cstdint>

#define BATCH  8192
#define SEQ    100
#define EMBED  50
#define HID    20
#define NLABEL 15
#define VOCAB  50000

// Precomputed P[v][64] = rearranged(emb_table[v] @ W1 + bi1), owner-major:
// owner q (0..3) gets 16 slots: [0..4]=z cols q*5.., [5..9]=r, [10..14]=h, [15]=pad
__device__ float g_P[VOCAB * 64];

// ---------------- helpers ----------------
__device__ __forceinline__ float tanha(float x) {
    float y;
    asm("tanh.approx.f32 %0, %1;" : "=f"(y) : "f"(x));
    return y;
}
// rearranged slot index (0..63) -> original gate column (0..59), or -1 pad
__device__ __forceinline__ int remap_col(int j64) {
    int q = j64 >> 4;
    int jj = j64 & 15;
    if (jj >= 15) return -1;
    int g = jj / 5;
    int l = jj - g * 5;
    return g * HID + q * 5 + l;
}
__device__ __forceinline__ unsigned pack_h2(float lo, float hi) {
    __half l = __float2half(lo), h = __float2half(hi);
    return ((unsigned)__half_as_ushort(h) << 16) | (unsigned)__half_as_ushort(l);
}
__device__ __forceinline__ void mma16816(float& c0, float& c1, float& c2, float& c3,
                                         unsigned a0, unsigned a1, unsigned a2, unsigned a3,
                                         unsigned b0, unsigned b1) {
    asm volatile(
        "mma.sync.aligned.m16n8k16.row.col.f32.f16.f16.f32 "
        "{%0,%1,%2,%3}, {%4,%5,%6,%7}, {%8,%9}, {%0,%1,%2,%3};"
        : "+f"(c0), "+f"(c1), "+f"(c2), "+f"(c3)
        : "r"(a0), "r"(a1), "r"(a2), "r"(a3), "r"(b0), "r"(b1));
}

// ---------------- P precompute ----------------
#define VPB 64
__global__ void __launch_bounds__(256) prep_P_kernel(const float* __restrict__ emb,
                                                     const float* __restrict__ W1,
                                                     const float* __restrict__ b1) {
    __shared__ __align__(16) float W1r[EMBED][64];
    __shared__ float biasr[64];
    __shared__ float embs[VPB][EMBED];
    int tid = threadIdx.x;
    for (int d = tid; d < EMBED * 64; d += 256) {
        int k = d >> 6, j = d & 63;
        int src = remap_col(j);
        W1r[k][j] = (src >= 0) ? W1[k * (3 * HID) + src] : 0.0f;
    }
    if (tid < 64) {
        int src = remap_col(tid);
        biasr[tid] = (src >= 0) ? b1[src] : 0.0f;
    }
    int v0 = blockIdx.x * VPB;
    for (int i = tid; i < VPB * EMBED; i += 256) {
        int vv = i / EMBED, k = i - vv * EMBED;
        int v = v0 + vv;
        embs[vv][k] = (v < VOCAB) ? emb[v * EMBED + k] : 0.0f;
    }
    __syncthreads();
    int d = tid & 63;
    int vbase = tid >> 6;
    #pragma unroll
    for (int i = 0; i < 16; i++) {
        int vl = vbase + 4 * i;
        int v = v0 + vl;
        if (v >= VOCAB) continue;
        float acc = biasr[d];
        #pragma unroll
        for (int k = 0; k < EMBED; k++)
            acc = fmaf(embs[vl][k], W1r[k][d], acc);
        g_P[v * 64 + d] = acc;
    }
}

// ---------------- main fused GRU kernel (tensor-core) ----------------
// 32 rows/block, 128 threads (4 warps). Per step one mma pass computes all
// three preact blocks [32 x 192]: cols 0-63 = U1*h1, 64-127 = W2*h1,
// 128-191 = U2*h2 (cols within each 64-block are owner-major rearranged,
// matching g_P). Weights live in B-fragments in REGISTERS for all 100 steps
// (zero weight smem traffic); biases folded via constant-1 at k=20.
// Gate phase: 4 threads/row (q = owner), state h1o/h2o kept fp32 in regs;
// fp16 h written to smem only as next step's A operand.
// Warp w: Mtile mt=w>>1 (rows 16mt..), nhalf nh=w&1 (Ntiles 12nh..12nh+11).
#define RPB     32
#define BLOCK2  128
#define HSTR    40          // halves per h-smem row (conflict-free: 40*2B=80B)
#define PSTR    200         // floats per preact-smem row

__global__ void __launch_bounds__(BLOCK2) gru_mma_kernel(
    const int*   __restrict__ x,
    const float* __restrict__ U1,
    const float* __restrict__ b1,
    const float* __restrict__ W2,
    const float* __restrict__ U2,
    const float* __restrict__ b2,
    const float* __restrict__ Wd,
    const float* __restrict__ bd,
    float*       __restrict__ out) {

    __shared__ __align__(16) __half h1s[RPB * HSTR];     // 2560 B
    __shared__ __align__(16) __half h2s[RPB * HSTR];     // 2560 B
    __shared__ __align__(16) float  ps[RPB * PSTR];      // 25600 B
    __shared__ __align__(16) float  sbr1[64];
    __shared__ __align__(16) float  sWd[HID * 16];
    __shared__ float sbd[16];

    int tid  = threadIdx.x;
    int lane = tid & 31;
    int w    = tid >> 5;
    int mt   = w >> 1;
    int nh   = w & 1;
    int lr   = lane >> 2;   // fragment row within tile
    int lc   = lane & 3;    // fragment col group

    // ---- stage bias (owner-major) + head weights ----
    if (tid < 64) {
        int src = remap_col(tid);
        sbr1[tid] = (src >= 0) ? b1[3 * HID + src] : 0.0f;
    }
    for (int d = tid; d < HID * 16; d += BLOCK2) {
        int k = d >> 4, j = d & 15;
        sWd[d] = (j < NLABEL) ? Wd[k * NLABEL + j] : 0.0f;
    }
    if (tid < 16) sbd[tid] = (tid < NLABEL) ? bd[tid] : 0.0f;

    // ---- zero h smem; col 20 = 1.0 (bias row) ----
    for (int d = tid; d < RPB * HSTR; d += BLOCK2) { h1s[d] = __ushort_as_half(0); h2s[d] = __ushort_as_half(0); }
    __syncthreads();
    if (tid < RPB) {
        h1s[tid * HSTR + 20] = __float2half(1.0f);
        h2s[tid * HSTR + 20] = __float2half(1.0f);
    }

    // ---- build B fragments in registers (persist all steps) ----
    // Wcat col n: blk = n>>6 (0=U1,1=W2,2=U2), c = n&63 owner-major.
    // row k: k<20 -> M[blk][k*60+src]; k==20 -> bias; else 0.
    unsigned Bf0[24], Bf1[24];   // [tile*2 + kstep]
    {
        int n = (12 * nh + 0) * 8;   // recomputed in loop
        (void)n;
        #pragma unroll
        for (int i = 0; i < 12; i++) {
            int nn  = (12 * nh + i) * 8 + lr;
            int blk = nn >> 6, c = nn & 63;
            int src = remap_col(c);
            const float* M  = (blk == 0) ? U1 : (blk == 1) ? W2 : U2;
            const float* Bb = (blk == 0) ? b1 : b2;
            int boff = (blk == 1) ? 0 : 60;
            #pragma unroll
            for (int ks = 0; ks < 2; ks++) {
                int k0 = ks * 16 + lc * 2;
                float v00 = 0.f, v01 = 0.f, v10 = 0.f, v11 = 0.f;
                if (src >= 0) {
                    if (k0 < 20)     v00 = M[k0 * 60 + src];
                    else if (k0 == 20) v00 = Bb[boff + src];
                    int k1 = k0 + 1;
                    if (k1 < 20)     v01 = M[k1 * 60 + src];
                    else if (k1 == 20) v01 = Bb[boff + src];
                    int k8 = k0 + 8;
                    if (k8 < 20)     v10 = M[k8 * 60 + src];
                    else if (k8 == 20) v10 = Bb[boff + src];
                    int k9 = k0 + 9;
                    if (k9 < 20)     v11 = M[k9 * 60 + src];
                    else if (k9 == 20) v11 = Bb[boff + src];
                }
                Bf0[i * 2 + ks] = pack_h2(v00, v01);
                Bf1[i * 2 + ks] = pack_h2(v10, v11);
            }
        }
    }

    // ---- gate-thread identity & state ----
    int rw = tid >> 2;            // row 0..31
    int q  = tid & 3;             // owner
    int row_g = blockIdx.x * RPB + rw;
    const int* xr = x + (size_t)row_g * SEQ;

    float h1o[5], h2o[5];
    #pragma unroll
    for (int i = 0; i < 5; i++) { h1o[i] = 0.f; h2o[i] = 0.f; }

    __syncthreads();

    // ---- prologue: GRU1(0) from px(0) + br1 (h1(-1)=0) ----
    int tok = xr[0];
    {
        const float4* pp = reinterpret_cast<const float4*>(g_P + (size_t)tok * 64 + q * 16);
        float4 p0 = pp[0], p1 = pp[1], p2 = pp[2], p3 = pp[3];
        float px[16] = {p0.x,p0.y,p0.z,p0.w, p1.x,p1.y,p1.z,p1.w,
                        p2.x,p2.y,p2.z,p2.w, p3.x,p3.y,p3.z,p3.w};
        #pragma unroll
        for (int i = 0; i < 5; i++) {
            float c0 = sbr1[q * 16 + i];
            float c1 = sbr1[q * 16 + 5 + i];
            float c2 = sbr1[q * 16 + 10 + i];
            float zt = tanha(0.5f * (px[i] + c0));
            float r  = 0.5f + 0.5f * tanha(0.5f * (px[5 + i] + c1));
            float hh = tanha(px[10 + i] + r * c2);
            h1o[i] = 0.5f * hh - 0.5f * zt * hh;
            h1s[rw * HSTR + q * 5 + i] = __float2half(h1o[i]);
        }
    }
    int tok_n = xr[1];
    __syncthreads();

    // ---- main loop: iter t computes GRU2(t) and GRU1(t+1) ----
    for (int t = 0; t < SEQ; t++) {
        // prefetch px(t+1) (in flight during mma)
        const float4* pp = reinterpret_cast<const float4*>(g_P + (size_t)tok_n * 64 + q * 16);
        float4 p0 = pp[0], p1 = pp[1], p2 = pp[2], p3 = pp[3];
        int t2 = t + 2;
        tok_n = xr[(t2 < SEQ) ? t2 : (SEQ - 1)];

        // ---- mma phase ----
        unsigned A1[2][4], A2[2][4];
        {
            int rbyte = (16 * mt + lr) * HSTR;      // half index
            #pragma unroll
            for (int ks = 0; ks < 2; ks++) {
                int cbase = ks * 16 + lc * 2;
                A1[ks][0] = *reinterpret_cast<const unsigned*>(&h1s[rbyte + cbase]);
                A1[ks][1] = *reinterpret_cast<const unsigned*>(&h1s[rbyte + 8 * HSTR + cbase]);
                A1[ks][2] = *reinterpret_cast<const unsigned*>(&h1s[rbyte + cbase + 8]);
                A1[ks][3] = *reinterpret_cast<const unsigned*>(&h1s[rbyte + 8 * HSTR + cbase + 8]);
            }
            if (nh == 1) {
                #pragma unroll
                for (int ks = 0; ks < 2; ks++) {
                    int cbase = ks * 16 + lc * 2;
                    A2[ks][0] = *reinterpret_cast<const unsigned*>(&h2s[rbyte + cbase]);
                    A2[ks][1] = *reinterpret_cast<const unsigned*>(&h2s[rbyte + 8 * HSTR + cbase]);
                    A2[ks][2] = *reinterpret_cast<const unsigned*>(&h2s[rbyte + cbase + 8]);
                    A2[ks][3] = *reinterpret_cast<const unsigned*>(&h2s[rbyte + 8 * HSTR + cbase + 8]);
                }
            }
        }
        float C[12][4];
        #pragma unroll
        for (int i = 0; i < 12; i++) { C[i][0] = 0.f; C[i][1] = 0.f; C[i][2] = 0.f; C[i][3] = 0.f; }
        #pragma unroll
        for (int i = 0; i < 12; i++) {
            bool useH2 = ((12 * nh + i) >= 16);   // cols >= 128 -> U2*h2
            #pragma unroll
            for (int ks = 0; ks < 2; ks++) {
                const unsigned* A = useH2 ? A2[ks] : A1[ks];
                mma16816(C[i][0], C[i][1], C[i][2], C[i][3],
                         A[0], A[1], A[2], A[3],
                         Bf0[i * 2 + ks], Bf1[i * 2 + ks]);
            }
        }
        // store preacts
        #pragma unroll
        for (int i = 0; i < 12; i++) {
            int cn = (12 * nh + i) * 8 + 2 * lc;
            int rb = (16 * mt + lr) * PSTR;
            *reinterpret_cast<float2*>(&ps[rb + cn]) = make_float2(C[i][0], C[i][1]);
            *reinterpret_cast<float2*>(&ps[rb + 8 * PSTR + cn]) = make_float2(C[i][2], C[i][3]);
        }
        __syncthreads();

        // ---- gate phase ----
        {
            const float4* pa = reinterpret_cast<const float4*>(&ps[rw * PSTR + q * 16]);
            const float4* px4 = reinterpret_cast<const float4*>(&ps[rw * PSTR + 64 + q * 16]);
            const float4* ph4 = reinterpret_cast<const float4*>(&ps[rw * PSTR + 128 + q * 16]);
            float rA[16], rX[16], rH[16];
            #pragma unroll
            for (int j = 0; j < 4; j++) {
                float4 va = pa[j];  rA[4*j]=va.x; rA[4*j+1]=va.y; rA[4*j+2]=va.z; rA[4*j+3]=va.w;
                float4 vx = px4[j]; rX[4*j]=vx.x; rX[4*j+1]=vx.y; rX[4*j+2]=vx.z; rX[4*j+3]=vx.w;
                float4 vh = ph4[j]; rH[4*j]=vh.x; rH[4*j+1]=vh.y; rH[4*j+2]=vh.z; rH[4*j+3]=vh.w;
            }
            float px[16] = {p0.x,p0.y,p0.z,p0.w, p1.x,p1.y,p1.z,p1.w,
                            p2.x,p2.y,p2.z,p2.w, p3.x,p3.y,p3.z,p3.w};
            // GRU2(t)
            #pragma unroll
            for (int i = 0; i < 5; i++) {
                float zt = tanha(0.5f * (rX[i] + rH[i]));
                float r  = 0.5f + 0.5f * tanha(0.5f * (rX[5+i] + rH[5+i]));
                float hh = tanha(rX[10+i] + r * rH[10+i]);
                float ho = h2o[i];
                h2o[i] = 0.5f * (ho + hh) + 0.5f * zt * (ho - hh);
                h2s[rw * HSTR + q * 5 + i] = __float2half(h2o[i]);
            }
            // GRU1(t+1)
            #pragma unroll
            for (int i = 0; i < 5; i++) {
                float zt = tanha(0.5f * (px[i] + rA[i]));
                float r  = 0.5f + 0.5f * tanha(0.5f * (px[5+i] + rA[5+i]));
                float hh = tanha(px[10+i] + r * rA[10+i]);
                float ho = h1o[i];
                h1o[i] = 0.5f * (ho + hh) + 0.5f * zt * (ho - hh);
                h1s[rw * HSTR + q * 5 + i] = __float2half(h1o[i]);
            }
        }
        __syncthreads();
    }

    // ---- dense head ----
    #pragma unroll
    for (int i = 0; i < 5; i++)
        ps[rw * PSTR + q * 5 + i] = h2o[i];
    __syncthreads();
    {
        float hv[HID];
        #pragma unroll
        for (int j = 0; j < 5; j++) {
            float4 v = *reinterpret_cast<const float4*>(&ps[rw * PSTR + 4 * j]);
            hv[4*j] = v.x; hv[4*j+1] = v.y; hv[4*j+2] = v.z; hv[4*j+3] = v.w;
        }
        #pragma unroll
        for (int c = 0; c < 4; c++) {
            int col = q * 4 + c;
            if (col >= NLABEL) break;
            float acc = sbd[col];
            #pragma unroll
            for (int k = 0; k < HID; k++)
                acc = fmaf(hv[k], sWd[k * 16 + col], acc);
            out[(size_t)row_g * NLABEL + col] = acc;
        }
    }
}

// ---------------- launch ----------------
extern "C" void kernel_launch(void* const* d_in, const int* in_sizes, int n_in,
                              void* d_out, int out_size) {
    const int*   x    = (const int*)  d_in[0];
    const float* emb  = (const float*)d_in[1];
    const float* W1   = (const float*)d_in[2];
    const float* U1   = (const float*)d_in[3];
    const float* b1   = (const float*)d_in[4];
    const float* W2   = (const float*)d_in[5];
    const float* U2   = (const float*)d_in[6];
    const float* b2   = (const float*)d_in[7];
    const float* Wd   = (const float*)d_in[8];
    const float* bd   = (const float*)d_in[9];
    float* out = (float*)d_out;

    prep_P_kernel<<<(VOCAB + VPB - 1) / VPB, 256>>>(emb, W1, b1);
    gru_mma_kernel<<<BATCH / RPB, BLOCK2>>>(x, U1, b1, W2, U2, b2, Wd, bd, out);
}